// round 16
// baseline (speedup 1.0000x reference)
#include <cuda_runtime.h>
#include <cuda_bf16.h>
#include <cstdint>

#define N_ITEMS 500000
#define DIM 64
#define BATCH 1024
#define QB 256              // queries per CTA (8 warps x 32 rows)
#define THREADS 256
#define ITEM_TILE 64
#define CHUNK 4096          // items per CTA chunk -> 64 tiles
#define NCHUNKS 123
#define N_PAD (NCHUNKS * CHUNK)              // 503808, zero-padded bf16 copy
#define TILES_PER_CHUNK (CHUNK / ITEM_TILE)  // 64
#define MARGIN 1.0f         // >= 2*eps(bf16 dot) ~ 0.4 worst-case; 2.5x safety
#define NINF __uint_as_float(0xFF800000u)
#define FULL 0xFFFFFFFFu

// Scratch (static __device__ arrays -- the sanctioned mechanism)
__device__ unsigned long long g_best[BATCH];             // exact packed best
__device__ unsigned g_amax[BATCH];                       // approx max (ordered f32)
__device__ __nv_bfloat16 g_emb16[(size_t)N_PAD * DIM];   // 64.5 MB bf16 copy

__device__ __forceinline__ unsigned f2ord(float f) {
    unsigned b = __float_as_uint(f);
    return (b & 0x80000000u) ? ~b : (b | 0x80000000u);
}
__device__ __forceinline__ float ord2f(unsigned o) {
    unsigned b = (o & 0x80000000u) ? (o & 0x7FFFFFFFu) : ~o;
    return __uint_as_float(b);
}
__device__ __forceinline__ unsigned pack_bf16x2(float x, float y) {
    __nv_bfloat162 p = __floats2bfloat162_rn(x, y);
    return *(unsigned*)&p;
}

__global__ void reset_kernel() {
    int i = blockIdx.x * blockDim.x + threadIdx.x;
    if (i < BATCH) {
        g_best[i] = ((unsigned long long)f2ord(NINF) << 32) | 0xFFFFFFFFull;
        g_amax[i] = f2ord(NINF);
    }
}

// fp32 -> bf16 preconversion (zero-pad beyond N_ITEMS)
__global__ void convert_kernel(const float* __restrict__ emb) {
    const int total = N_PAD * (DIM / 4);
    const int real  = N_ITEMS * (DIM / 4);
    for (int i = blockIdx.x * blockDim.x + threadIdx.x; i < total;
         i += gridDim.x * blockDim.x) {
        float4 v = (i < real) ? __ldg((const float4*)emb + i)
                              : make_float4(0.f, 0.f, 0.f, 0.f);
        ((uint2*)g_emb16)[i] = make_uint2(pack_bf16x2(v.x, v.y),
                                          pack_bf16x2(v.z, v.w));
    }
}

// Exact fp32 rescore; accumulation order IDENTICAL to R6 -> deterministic
// cross-chunk argmax via packed atomicMax (tie -> smaller index).
__device__ __forceinline__ void rescore(const float* __restrict__ emb,
                                        int qrow, int j, float& be, int& bi) {
    const float4* qa = (const float4*)(emb + (size_t)qrow * DIM);
    const float4* ja = (const float4*)(emb + (size_t)j * DIM);
    float a0 = 0.f, a1 = 0.f;
    #pragma unroll
    for (int p = 0; p < 16; p += 2) {
        float4 x0 = __ldg(qa + p),     y0 = __ldg(ja + p);
        float4 x1 = __ldg(qa + p + 1), y1 = __ldg(ja + p + 1);
        a0 = fmaf(x0.x, y0.x, a0); a0 = fmaf(x0.y, y0.y, a0);
        a0 = fmaf(x0.z, y0.z, a0); a0 = fmaf(x0.w, y0.w, a0);
        a1 = fmaf(x1.x, y1.x, a1); a1 = fmaf(x1.y, y1.y, a1);
        a1 = fmaf(x1.z, y1.z, a1); a1 = fmaf(x1.w, y1.w, a1);
    }
    float acc = a0 + a1;
    if (acc > be || (acc == be && j < bi)) { be = acc; bi = j; }
}

__device__ __forceinline__ void mma16816(float c[4], const unsigned a[4],
                                         unsigned b0, unsigned b1) {
    asm volatile(
        "mma.sync.aligned.m16n8k16.row.col.f32.bf16.bf16.f32 "
        "{%0,%1,%2,%3}, {%4,%5,%6,%7}, {%8,%9}, {%0,%1,%2,%3};"
        : "+f"(c[0]), "+f"(c[1]), "+f"(c[2]), "+f"(c[3])
        : "r"(a[0]), "r"(a[1]), "r"(a[2]), "r"(a[3]), "r"(b0), "r"(b1));
}

// Warp owns 32 query rows (two 16-row A sets) -> each B fragment feeds 4 MMAs
// (MMA:LDSM = 4:1, halving L1/shared pressure vs R13).
// PASS 1: pure bf16 max-scan. PASS 2: fixed-threshold band + exact rescore.
template <int PASS>
__global__ __launch_bounds__(THREADS, 2)
void sim_pass(const float* __restrict__ emb,
              const int* __restrict__ item_idx) {
    __shared__ __align__(16) __nv_bfloat16 qs[QB * DIM];             // 32 KB
    __shared__ __align__(16) __nv_bfloat16 its[2 * ITEM_TILE * DIM]; // 16 KB 2buf
    __shared__ int selfs[QB];

    const int tid   = threadIdx.x;
    const int warp  = tid >> 5;
    const int lane  = tid & 31;
    const int qbase = blockIdx.y * QB;
    const int wq    = warp * 32;          // 32 rows per warp

    // ---- self indices (item_idx is int32 under JAX default promotion)
    for (int q = tid; q < QB; q += THREADS) {
        int s = item_idx[qbase + q] - 1;
        if (s < 0) s += N_ITEMS;               // python negative-index wrap
        selfs[q] = max(0, min(s, N_ITEMS - 1));
    }
    __syncthreads();

    // ---- stage query rows as bf16 (linear 128B rows)
    for (int i = tid; i < QB * (DIM / 4); i += THREADS) {
        int q = i >> 4, p = i & 15;
        float4 v = __ldg((const float4*)(emb + (size_t)selfs[q] * DIM) + p);
        *(uint2*)((char*)qs + q * 128 + p * 8) =
            make_uint2(pack_bf16x2(v.x, v.y), pack_bf16x2(v.z, v.w));
    }
    __syncthreads();

    // ---- A fragments: two 16-row sets, K=64, resident in 32 regs
    unsigned a[2][4][4];
    #pragma unroll
    for (int s = 0; s < 2; s++) {
        unsigned qaddr = (unsigned)__cvta_generic_to_shared(qs)
            + (unsigned)((wq + s * 16 + (lane & 15)) * 128 + (lane >> 4) * 16);
        #pragma unroll
        for (int kt = 0; kt < 4; kt++) {
            asm volatile("ldmatrix.sync.aligned.m8n8.x4.shared.b16 {%0,%1,%2,%3}, [%4];"
                         : "=r"(a[s][kt][0]), "=r"(a[s][kt][1]),
                           "=r"(a[s][kt][2]), "=r"(a[s][kt][3])
                         : "r"(qaddr + kt * 32));
        }
    }

    const int t4 = lane & 3;            // column pair within mma
    const int g  = lane >> 2;           // row within 16-row block
    // per-set row selves: set s covers rows wq+s*16+g and wq+s*16+g+8
    int selfA[2], selfB[2];
    #pragma unroll
    for (int s = 0; s < 2; s++) {
        selfA[s] = selfs[wq + s * 16 + g];
        selfB[s] = selfs[wq + s * 16 + g + 8];
    }
    const int myrow_self = selfs[wq + lane];   // lane <-> row bijection (32 rows)

    float runA[2] = {NINF, NINF}, runB[2] = {NINF, NINF};
    float thrA[2] = {NINF, NINF}, thrB[2] = {NINF, NINF};
    if (PASS == 2) {
        #pragma unroll
        for (int s = 0; s < 2; s++) {
            thrA[s] = ord2f(g_amax[qbase + wq + s * 16 + g]) - MARGIN;
            thrB[s] = ord2f(g_amax[qbase + wq + s * 16 + g + 8]) - MARGIN;
        }
    }
    float beA[2] = {NINF, NINF}, beB[2] = {NINF, NINF};
    int   biA[2] = {0x7FFFFFFF, 0x7FFFFFFF}, biB[2] = {0x7FFFFFFF, 0x7FFFFFFF};

    const unsigned its_base = (unsigned)__cvta_generic_to_shared(its);
    const int r  = lane & 7;            // ldmatrix.x4 B addressing
    const int mk = (lane >> 3) & 1;
    const int mg = (lane >> 4) & 1;

    const int tile0 = blockIdx.x * TILES_PER_CHUNK;

    auto issue_tile = [&](int gt, int buf) {
        #pragma unroll
        for (int s = 0; s < 2; s++) {
            int seg = tid + s * THREADS;              // 16B segments
            int it = seg >> 3, p16 = seg & 7;
            const char* src = (const char*)g_emb16 + (size_t)gt * 8192 + seg * 16;
            unsigned dst = its_base + buf * 8192 + it * 128
                         + ((p16 * 16) ^ ((it & 7) * 16));
            asm volatile("cp.async.cg.shared.global [%0], [%1], 16;"
                         :: "r"(dst), "l"(src));
        }
    };

    issue_tile(tile0, 0);
    asm volatile("cp.async.commit_group;");
    issue_tile(tile0 + 1, 1);
    asm volatile("cp.async.commit_group;");

    for (int t = 0; t < TILES_PER_CHUNK; t++) {
        asm volatile("cp.async.wait_group 1;");
        __syncthreads();

        const int tb = (tile0 + t) * ITEM_TILE;
        const unsigned bufb = its_base + (t & 1) * 8192;
        const bool need_mask =
            (__ballot_sync(FULL, (unsigned)(myrow_self - tb) < (unsigned)ITEM_TILE) != 0u)
            || (tb + ITEM_TILE > N_ITEMS);

        #pragma unroll
        for (int ng = 0; ng < 8; ng += 2) {
            float c[2][2][4];   // [A-set][item-half][frag]
            #pragma unroll
            for (int s = 0; s < 2; s++)
                #pragma unroll
                for (int h = 0; h < 2; h++)
                    #pragma unroll
                    for (int e = 0; e < 4; e++) c[s][h][e] = 0.f;

            #pragma unroll
            for (int kt = 0; kt < 4; kt++) {
                unsigned addr = bufb + (unsigned)((ng * 8 + mg * 8 + r) * 128)
                              + (unsigned)((kt * 32 + mk * 16) ^ (r * 16));
                unsigned b0, b1, b2, b3;
                asm volatile("ldmatrix.sync.aligned.m8n8.x4.shared.b16 {%0,%1,%2,%3}, [%4];"
                             : "=r"(b0), "=r"(b1), "=r"(b2), "=r"(b3) : "r"(addr));
                mma16816(c[0][0], a[0][kt], b0, b1);
                mma16816(c[0][1], a[0][kt], b2, b3);
                mma16816(c[1][0], a[1][kt], b0, b1);
                mma16816(c[1][1], a[1][kt], b2, b3);
            }

            #pragma unroll
            for (int s = 0; s < 2; s++) {
                #pragma unroll
                for (int h = 0; h < 2; h++) {
                    float* cc = c[s][h];
                    int jb = tb + (ng + h) * 8;
                    int col0 = jb + 2 * t4, col1 = col0 + 1;
                    if (PASS == 1) {
                        if (need_mask) {   // exclude self/padded cols from max
                            if (col0 == selfA[s] || col0 >= N_ITEMS) cc[0] = NINF;
                            if (col1 == selfA[s] || col1 >= N_ITEMS) cc[1] = NINF;
                            if (col0 == selfB[s] || col0 >= N_ITEMS) cc[2] = NINF;
                            if (col1 == selfB[s] || col1 >= N_ITEMS) cc[3] = NINF;
                        }
                        runA[s] = fmaxf(runA[s], fmaxf(cc[0], cc[1]));
                        runB[s] = fmaxf(runB[s], fmaxf(cc[2], cc[3]));
                    } else {
                        if (fmaxf(cc[0], cc[1]) >= thrA[s] ||
                            fmaxf(cc[2], cc[3]) >= thrB[s]) {
                            if (cc[0] >= thrA[s] && col0 != selfA[s] && col0 < N_ITEMS)
                                rescore(emb, selfA[s], col0, beA[s], biA[s]);
                            if (cc[1] >= thrA[s] && col1 != selfA[s] && col1 < N_ITEMS)
                                rescore(emb, selfA[s], col1, beA[s], biA[s]);
                            if (cc[2] >= thrB[s] && col0 != selfB[s] && col0 < N_ITEMS)
                                rescore(emb, selfB[s], col0, beB[s], biB[s]);
                            if (cc[3] >= thrB[s] && col1 != selfB[s] && col1 < N_ITEMS)
                                rescore(emb, selfB[s], col1, beB[s], biB[s]);
                        }
                    }
                }
            }
        }

        __syncthreads();   // all warps done with buf[t&1] before refill
        if (t + 2 < TILES_PER_CHUNK) issue_tile(tile0 + t + 2, t & 1);
        asm volatile("cp.async.commit_group;");  // empty group ok, keeps count
    }

    if (PASS == 1) {
        #pragma unroll
        for (int s = 0; s < 2; s++) {
            runA[s] = fmaxf(runA[s], __shfl_xor_sync(FULL, runA[s], 1));
            runA[s] = fmaxf(runA[s], __shfl_xor_sync(FULL, runA[s], 2));
            runB[s] = fmaxf(runB[s], __shfl_xor_sync(FULL, runB[s], 1));
            runB[s] = fmaxf(runB[s], __shfl_xor_sync(FULL, runB[s], 2));
        }
        if (t4 == 0) {
            #pragma unroll
            for (int s = 0; s < 2; s++) {
                atomicMax(&g_amax[qbase + wq + s * 16 + g],     f2ord(runA[s]));
                atomicMax(&g_amax[qbase + wq + s * 16 + g + 8], f2ord(runB[s]));
            }
        }
    } else {
        #pragma unroll
        for (int s = 0; s < 2; s++) {
            #pragma unroll
            for (int m = 1; m <= 2; m <<= 1) {
                float so = __shfl_xor_sync(FULL, beA[s], m);
                int   io = __shfl_xor_sync(FULL, biA[s], m);
                if (so > beA[s] || (so == beA[s] && io < biA[s])) { beA[s] = so; biA[s] = io; }
                so = __shfl_xor_sync(FULL, beB[s], m);
                io = __shfl_xor_sync(FULL, biB[s], m);
                if (so > beB[s] || (so == beB[s] && io < biB[s])) { beB[s] = so; biB[s] = io; }
            }
        }
        if (t4 == 0) {
            #pragma unroll
            for (int s = 0; s < 2; s++) {
                if (beA[s] > NINF) {
                    unsigned long long pk =
                        ((unsigned long long)f2ord(beA[s]) << 32) | (unsigned)(~biA[s]);
                    atomicMax(&g_best[qbase + wq + s * 16 + g], pk);
                }
                if (beB[s] > NINF) {
                    unsigned long long pk =
                        ((unsigned long long)f2ord(beB[s]) << 32) | (unsigned)(~biB[s]);
                    atomicMax(&g_best[qbase + wq + s * 16 + g + 8], pk);
                }
            }
        }
    }
}

__global__ void finalize_kernel(const float* __restrict__ minv,
                                const float* __restrict__ maxv,
                                float* __restrict__ out) {
    int i = blockIdx.x * blockDim.x + threadIdx.x;
    if (i < BATCH) {
        unsigned long long p = g_best[i];
        float raw = ord2f((unsigned)(p >> 32));
        int   idx = (int)(~(unsigned)(p & 0xFFFFFFFFull));
        float mn = minv[0], mx = maxv[0];
        float score = (raw - mn) / (mx - mn);
        out[i]         = (float)(idx + 1);   // indices (argmax + 1), exact < 2^24
        out[BATCH + i] = score;              // normalized scores (fp32 output)
    }
}

extern "C" void kernel_launch(void* const* d_in, const int* in_sizes, int n_in,
                              void* d_out, int out_size) {
    const float* emb = (const float*)d_in[0];
    const int*   idx = (const int*)d_in[1];
    const float* mn  = (const float*)d_in[2];
    const float* mx  = (const float*)d_in[3];

    reset_kernel<<<(BATCH + 255) / 256, 256>>>();
    convert_kernel<<<2048, 256>>>(emb);

    dim3 grid(NCHUNKS, BATCH / QB);
    sim_pass<1><<<grid, THREADS>>>(emb, idx);   // approx max per query
    sim_pass<2><<<grid, THREADS>>>(emb, idx);   // band detect + exact rescore

    finalize_kernel<<<(BATCH + 255) / 256, 256>>>(mn, mx, (float*)d_out);
}

// round 17
// speedup vs baseline: 1.3306x; 1.3306x over previous
#include <cuda_runtime.h>
#include <cuda_bf16.h>
#include <cstdint>

#define N_ITEMS 500000
#define DIM 64
#define BATCH 1024
#define QB 128              // queries per CTA (8 warps x 16 rows)
#define THREADS 256
#define ITEM_TILE 64
#define NCHUNKS 123
#define TILES_FULL 64       // tiles per CTA, full pass (4096 items)
#define TILES_SAMP 8        // tiles per CTA, sample pass (512 items)
#define SAMP_X 64           // sample grid.x -> 64*512 = 32768 items sampled
#define N_PAD (NCHUNKS * TILES_FULL * ITEM_TILE)   // 503808, zero-padded
#define MARGIN 1.0f         // >= 2*eps(bf16 dot) ~ 0.35; ~3x safety
#define NINF __uint_as_float(0xFF800000u)
#define FULL 0xFFFFFFFFu

// Scratch (static __device__ arrays -- the sanctioned mechanism)
__device__ unsigned long long g_best[BATCH];             // exact packed best
__device__ unsigned g_amax[BATCH];                       // sampled approx max
__device__ __nv_bfloat16 g_emb16[(size_t)N_PAD * DIM];   // 64.5 MB bf16 copy

__device__ __forceinline__ unsigned f2ord(float f) {
    unsigned b = __float_as_uint(f);
    return (b & 0x80000000u) ? ~b : (b | 0x80000000u);
}
__device__ __forceinline__ float ord2f(unsigned o) {
    unsigned b = (o & 0x80000000u) ? (o & 0x7FFFFFFFu) : ~o;
    return __uint_as_float(b);
}
__device__ __forceinline__ unsigned pack_bf16x2(float x, float y) {
    __nv_bfloat162 p = __floats2bfloat162_rn(x, y);
    return *(unsigned*)&p;
}

__global__ void reset_kernel() {
    int i = blockIdx.x * blockDim.x + threadIdx.x;
    if (i < BATCH) {
        g_best[i] = ((unsigned long long)f2ord(NINF) << 32) | 0xFFFFFFFFull;
        g_amax[i] = f2ord(NINF);
    }
}

// fp32 -> bf16 preconversion (zero-pad beyond N_ITEMS)
__global__ void convert_kernel(const float* __restrict__ emb) {
    const int total = N_PAD * (DIM / 4);
    const int real  = N_ITEMS * (DIM / 4);
    for (int i = blockIdx.x * blockDim.x + threadIdx.x; i < total;
         i += gridDim.x * blockDim.x) {
        float4 v = (i < real) ? __ldg((const float4*)emb + i)
                              : make_float4(0.f, 0.f, 0.f, 0.f);
        ((uint2*)g_emb16)[i] = make_uint2(pack_bf16x2(v.x, v.y),
                                          pack_bf16x2(v.z, v.w));
    }
}

// Exact fp32 rescore; accumulation order IDENTICAL to R6 -> deterministic
// cross-chunk argmax via packed atomicMax (tie -> smaller index).
__device__ __forceinline__ void rescore(const float* __restrict__ emb,
                                        int qrow, int j, float& be, int& bi) {
    const float4* qa = (const float4*)(emb + (size_t)qrow * DIM);
    const float4* ja = (const float4*)(emb + (size_t)j * DIM);
    float a0 = 0.f, a1 = 0.f;
    #pragma unroll
    for (int p = 0; p < 16; p += 2) {
        float4 x0 = __ldg(qa + p),     y0 = __ldg(ja + p);
        float4 x1 = __ldg(qa + p + 1), y1 = __ldg(ja + p + 1);
        a0 = fmaf(x0.x, y0.x, a0); a0 = fmaf(x0.y, y0.y, a0);
        a0 = fmaf(x0.z, y0.z, a0); a0 = fmaf(x0.w, y0.w, a0);
        a1 = fmaf(x1.x, y1.x, a1); a1 = fmaf(x1.y, y1.y, a1);
        a1 = fmaf(x1.z, y1.z, a1); a1 = fmaf(x1.w, y1.w, a1);
    }
    float acc = a0 + a1;
    if (acc > be || (acc == be && j < bi)) { be = acc; bi = j; }
}

__device__ __forceinline__ void mma16816(float c[4], const unsigned a[4],
                                         unsigned b0, unsigned b1) {
    asm volatile(
        "mma.sync.aligned.m16n8k16.row.col.f32.bf16.bf16.f32 "
        "{%0,%1,%2,%3}, {%4,%5,%6,%7}, {%8,%9}, {%0,%1,%2,%3};"
        : "+f"(c[0]), "+f"(c[1]), "+f"(c[2]), "+f"(c[3])
        : "r"(a[0]), "r"(a[1]), "r"(a[2]), "r"(a[3]), "r"(b0), "r"(b1));
}

// PASS 1 (TILES=TILES_SAMP): bf16 max over a 32k-item sample -> g_amax.
// PASS 2 (TILES=TILES_FULL): full scan, fixed threshold from sampled max,
// exact fp32 rescore of band members (~30 per query grid-wide).
template <int PASS, int TILES>
__global__ __launch_bounds__(THREADS, 2)
void sim_pass(const float* __restrict__ emb,
              const int* __restrict__ item_idx) {
    __shared__ __align__(16) __nv_bfloat16 qs[QB * DIM];             // 16 KB
    __shared__ __align__(16) __nv_bfloat16 its[2 * ITEM_TILE * DIM]; // 16 KB 2buf
    __shared__ int selfs[QB];

    const int tid   = threadIdx.x;
    const int warp  = tid >> 5;
    const int lane  = tid & 31;
    const int qbase = blockIdx.y * QB;
    const int wq    = warp * 16;

    // ---- self indices (item_idx is int32 under JAX default promotion)
    for (int q = tid; q < QB; q += THREADS) {
        int s = item_idx[qbase + q] - 1;
        if (s < 0) s += N_ITEMS;               // python negative-index wrap
        selfs[q] = max(0, min(s, N_ITEMS - 1));
    }
    __syncthreads();

    // ---- stage query rows as bf16 (linear 128B rows)
    for (int i = tid; i < QB * (DIM / 4); i += THREADS) {
        int q = i >> 4, p = i & 15;
        float4 v = __ldg((const float4*)(emb + (size_t)selfs[q] * DIM) + p);
        *(uint2*)((char*)qs + q * 128 + p * 8) =
            make_uint2(pack_bf16x2(v.x, v.y), pack_bf16x2(v.z, v.w));
    }
    __syncthreads();

    // ---- A fragments: warp's 16 query rows, K=64, resident in 16 regs
    unsigned a[4][4];
    {
        unsigned qaddr = (unsigned)__cvta_generic_to_shared(qs)
                       + (unsigned)((wq + (lane & 15)) * 128 + (lane >> 4) * 16);
        #pragma unroll
        for (int kt = 0; kt < 4; kt++) {
            asm volatile("ldmatrix.sync.aligned.m8n8.x4.shared.b16 {%0,%1,%2,%3}, [%4];"
                         : "=r"(a[kt][0]), "=r"(a[kt][1]), "=r"(a[kt][2]), "=r"(a[kt][3])
                         : "r"(qaddr + kt * 32));
        }
    }

    const int t4 = lane & 3;            // column pair within mma
    const int g  = lane >> 2;           // row within 16-row block
    const int self0 = selfs[wq + g];
    const int self1 = selfs[wq + g + 8];
    const int myrow_self = selfs[wq + (lane & 15)];

    float run0 = NINF, run1 = NINF;     // pass1: running approx max
    float thr0 = NINF, thr1 = NINF;     // pass2: fixed thresholds
    if (PASS == 2) {
        thr0 = ord2f(g_amax[qbase + wq + g]) - MARGIN;
        thr1 = ord2f(g_amax[qbase + wq + g + 8]) - MARGIN;
    }
    float be0 = NINF, be1 = NINF;       // pass2: exact best among rescored
    int   bi0 = 0x7FFFFFFF, bi1 = 0x7FFFFFFF;

    const unsigned its_base = (unsigned)__cvta_generic_to_shared(its);
    const int r  = lane & 7;            // ldmatrix.x4 B addressing
    const int mk = (lane >> 3) & 1;
    const int mg = (lane >> 4) & 1;

    const int tile0 = blockIdx.x * TILES;

    auto issue_tile = [&](int gt, int buf) {
        #pragma unroll
        for (int s = 0; s < 2; s++) {
            int seg = tid + s * THREADS;              // 16B segments
            int it = seg >> 3, p16 = seg & 7;
            const char* src = (const char*)g_emb16 + (size_t)gt * 8192 + seg * 16;
            unsigned dst = its_base + buf * 8192 + it * 128
                         + ((p16 * 16) ^ ((it & 7) * 16));
            asm volatile("cp.async.cg.shared.global [%0], [%1], 16;"
                         :: "r"(dst), "l"(src));
        }
    };

    issue_tile(tile0, 0);
    asm volatile("cp.async.commit_group;");
    issue_tile(tile0 + 1, 1);
    asm volatile("cp.async.commit_group;");

    for (int t = 0; t < TILES; t++) {
        asm volatile("cp.async.wait_group 1;");
        __syncthreads();

        const int tb = (tile0 + t) * ITEM_TILE;
        const unsigned bufb = its_base + (t & 1) * 8192;
        const bool need_mask =
            (__ballot_sync(FULL, (unsigned)(myrow_self - tb) < (unsigned)ITEM_TILE) != 0u)
            || (tb + ITEM_TILE > N_ITEMS);

        #pragma unroll
        for (int ng = 0; ng < 8; ng += 2) {
            float c0[4] = {0.f, 0.f, 0.f, 0.f};
            float c1[4] = {0.f, 0.f, 0.f, 0.f};
            #pragma unroll
            for (int kt = 0; kt < 4; kt++) {
                unsigned addr = bufb + (unsigned)((ng * 8 + mg * 8 + r) * 128)
                              + (unsigned)((kt * 32 + mk * 16) ^ (r * 16));
                unsigned b0, b1, b2, b3;
                asm volatile("ldmatrix.sync.aligned.m8n8.x4.shared.b16 {%0,%1,%2,%3}, [%4];"
                             : "=r"(b0), "=r"(b1), "=r"(b2), "=r"(b3) : "r"(addr));
                mma16816(c0, a[kt], b0, b1);
                mma16816(c1, a[kt], b2, b3);
            }
            #pragma unroll
            for (int half = 0; half < 2; half++) {
                float* c = half ? c1 : c0;
                int jb = tb + (ng + half) * 8;
                int col0 = jb + 2 * t4, col1 = col0 + 1;
                if (PASS == 1) {
                    if (need_mask) {   // exclude self and padded cols from max
                        if (col0 == self0 || col0 >= N_ITEMS) c[0] = NINF;
                        if (col1 == self0 || col1 >= N_ITEMS) c[1] = NINF;
                        if (col0 == self1 || col0 >= N_ITEMS) c[2] = NINF;
                        if (col1 == self1 || col1 >= N_ITEMS) c[3] = NINF;
                    }
                    run0 = fmaxf(run0, fmaxf(c[0], c[1]));
                    run1 = fmaxf(run1, fmaxf(c[2], c[3]));
                } else {
                    // fixed sampled thresholds; ~30 hits/query over whole grid
                    if (fmaxf(c[0], c[1]) >= thr0 || fmaxf(c[2], c[3]) >= thr1) {
                        if (c[0] >= thr0 && col0 != self0 && col0 < N_ITEMS)
                            rescore(emb, self0, col0, be0, bi0);
                        if (c[1] >= thr0 && col1 != self0 && col1 < N_ITEMS)
                            rescore(emb, self0, col1, be0, bi0);
                        if (c[2] >= thr1 && col0 != self1 && col0 < N_ITEMS)
                            rescore(emb, self1, col0, be1, bi1);
                        if (c[3] >= thr1 && col1 != self1 && col1 < N_ITEMS)
                            rescore(emb, self1, col1, be1, bi1);
                    }
                }
            }
        }

        __syncthreads();   // all warps done with buf[t&1] before refill
        if (t + 2 < TILES) issue_tile(tile0 + t + 2, t & 1);
        asm volatile("cp.async.commit_group;");  // empty group ok, keeps count
    }

    if (PASS == 1) {
        run0 = fmaxf(run0, __shfl_xor_sync(FULL, run0, 1));
        run0 = fmaxf(run0, __shfl_xor_sync(FULL, run0, 2));
        run1 = fmaxf(run1, __shfl_xor_sync(FULL, run1, 1));
        run1 = fmaxf(run1, __shfl_xor_sync(FULL, run1, 2));
        if (t4 == 0) {
            atomicMax(&g_amax[qbase + wq + g],     f2ord(run0));
            atomicMax(&g_amax[qbase + wq + g + 8], f2ord(run1));
        }
    } else {
        #pragma unroll
        for (int m = 1; m <= 2; m <<= 1) {
            float so = __shfl_xor_sync(FULL, be0, m);
            int   io = __shfl_xor_sync(FULL, bi0, m);
            if (so > be0 || (so == be0 && io < bi0)) { be0 = so; bi0 = io; }
            so = __shfl_xor_sync(FULL, be1, m);
            io = __shfl_xor_sync(FULL, bi1, m);
            if (so > be1 || (so == be1 && io < bi1)) { be1 = so; bi1 = io; }
        }
        if (t4 == 0) {
            if (be0 > NINF) {
                unsigned long long pk =
                    ((unsigned long long)f2ord(be0) << 32) | (unsigned)(~bi0);
                atomicMax(&g_best[qbase + wq + g], pk);
            }
            if (be1 > NINF) {
                unsigned long long pk =
                    ((unsigned long long)f2ord(be1) << 32) | (unsigned)(~bi1);
                atomicMax(&g_best[qbase + wq + g + 8], pk);
            }
        }
    }
}

__global__ void finalize_kernel(const float* __restrict__ minv,
                                const float* __restrict__ maxv,
                                float* __restrict__ out) {
    int i = blockIdx.x * blockDim.x + threadIdx.x;
    if (i < BATCH) {
        unsigned long long p = g_best[i];
        float raw = ord2f((unsigned)(p >> 32));
        int   idx = (int)(~(unsigned)(p & 0xFFFFFFFFull));
        float mn = minv[0], mx = maxv[0];
        float score = (raw - mn) / (mx - mn);
        out[i]         = (float)(idx + 1);   // indices (argmax + 1), exact < 2^24
        out[BATCH + i] = score;              // normalized scores (fp32 output)
    }
}

extern "C" void kernel_launch(void* const* d_in, const int* in_sizes, int n_in,
                              void* d_out, int out_size) {
    const float* emb = (const float*)d_in[0];
    const int*   idx = (const int*)d_in[1];
    const float* mn  = (const float*)d_in[2];
    const float* mx  = (const float*)d_in[3];

    reset_kernel<<<(BATCH + 255) / 256, 256>>>();
    convert_kernel<<<2048, 256>>>(emb);

    // pass 1: sampled approx max over 64*8*64 = 32768 items (6.5% of work)
    dim3 grid1(SAMP_X, BATCH / QB);
    sim_pass<1, TILES_SAMP><<<grid1, THREADS>>>(emb, idx);

    // pass 2: full scan, fixed threshold, exact rescore of band members
    dim3 grid2(NCHUNKS, BATCH / QB);
    sim_pass<2, TILES_FULL><<<grid2, THREADS>>>(emb, idx);

    finalize_kernel<<<(BATCH + 255) / 256, 256>>>(mn, mx, (float*)d_out);
}